// round 11
// baseline (speedup 1.0000x reference)
#include <cuda_runtime.h>
#include <cstdint>

// Problem constants
#define BB 8
#define CC 64
#define FF 3
#define HH 192
#define WW 192
#define HO 182
#define WO 182
#define C1S 0.01f
#define C2S 0.09f
#define INV_NPIX (1.0f/33124.0f)
#define NBAND 4
#define K1B 12

typedef unsigned long long u64;

// mu_f/sig_f per (b,f) plane, packed {mu,sig}; +2 pad for float4 overread
__device__ __align__(16) float2 g_musig[BB * FF * HO * WO + 2];
// per-band partial ssim sums [band][B][F][C]
__device__ float g_part[NBAND * BB * FF * CC];

// 11-tap gaussian (sigma=1.5)
__device__ __forceinline__ float wt(int i) {
    switch (i) {
        case 0: case 10: return 0.00102838f;
        case 1: case 9:  return 0.00759876f;
        case 2: case 8:  return 0.03600077f;
        case 3: case 7:  return 0.10936069f;
        case 4: case 6:  return 0.21300553f;
        default:         return 0.26601173f;
    }
}

// ---- packed f32x2 helpers (k1 only) ----
__device__ __forceinline__ u64 f2u(float a, float b) {
    u64 r; asm("mov.b64 %0, {%1, %2};" : "=l"(r) : "f"(a), "f"(b)); return r;
}
__device__ __forceinline__ void u2f(u64 v, float& a, float& b) {
    asm("mov.b64 {%0, %1}, %2;" : "=f"(a), "=f"(b) : "l"(v));
}
__device__ __forceinline__ u64 fma2(u64 a, u64 b, u64 c) {
    u64 d; asm("fma.rn.f32x2 %0, %1, %2, %3;" : "=l"(d) : "l"(a), "l"(b), "l"(c)); return d;
}
__device__ __forceinline__ u64 mul2(u64 a, u64 b) {
    u64 d; asm("mul.rn.f32x2 %0, %1, %2;" : "=l"(d) : "l"(a), "l"(b)); return d;
}

// scalar transposed-FIR push (imm-form FFMA, zero weight registers, rt 1)
__device__ __forceinline__ float fir_push(float (&P)[10], float h) {
    float out = fmaf(wt(10), h, P[0]);
#pragma unroll
    for (int m = 0; m < 9; m++) P[m] = fmaf(wt(9 - m), h, P[m + 1]);
    P[9] = wt(0) * h;
    return out;
}

// packed transposed-FIR push; W6[k] = {wt(k),wt(k)} for k=0..5
#define WP(i) (W6[(i) < 6 ? (i) : 10 - (i)])
__device__ __forceinline__ u64 fir_push2(u64 (&P)[10], u64 h, const u64 (&W6)[6]) {
    u64 out = fma2(WP(10), h, P[0]);
#pragma unroll
    for (int m = 0; m < 9; m++) P[m] = fma2(WP(9 - m), h, P[m + 1]);
    P[9] = mul2(WP(0), h);
    return out;
}

__device__ __forceinline__ uint32_t s2u(const void* p) {
    return (uint32_t)__cvta_generic_to_shared(p);
}
__device__ __forceinline__ void cp16(uint32_t dst, const void* src, bool pred) {
    int sz = pred ? 16 : 0;
    asm volatile("cp.async.ca.shared.global [%0], [%1], 16, %2;\n"
                 :: "r"(dst), "l"(src), "r"(sz));
}
#define CP_COMMIT() asm volatile("cp.async.commit_group;\n" ::: "memory")
#define CP_WAIT0()  asm volatile("cp.async.wait_group 0;\n" ::: "memory")

// ---------------------------------------------------------------------------
// K1: mu_f/sig_f planes. grid (24, 12 bands), 192 threads. (unchanged)
// ---------------------------------------------------------------------------
__global__ void __launch_bounds__(192) k1_musig(const float* __restrict__ xf) {
    const int bf = blockIdx.x;
    const int band = blockIdx.y;
    const int t = threadIdx.x;

    __shared__ float stage[2][4][WW];
    __shared__ __align__(16) float2 vsb[4][196];   // packed {f_blur, ff_blur}

    const int r0 = 16 * band;
    const int r1 = (band == K1B - 1) ? HO : 16 * (band + 1);
    const int NIT = 7;

    const float* plane = xf + (size_t)bf * HH * WW;

    const int lrw = t / 48, lkk = t % 48;
    const int hrw = t / 46, hcg = t % 46;
    const int j0 = 4 * hcg;

    u64 W6[6];
#pragma unroll
    for (int k = 0; k < 6; k++) W6[k] = f2u(wt(k), wt(k));

    u64 P[10];
#pragma unroll
    for (int m = 0; m < 10; m++) P[m] = f2u(0.f, 0.f);

    {
        int r = r0 + lrw;
        bool v = r < HH;
        int rc = v ? r : HH - 1;
        cp16(s2u(&stage[0][lrw][4 * lkk]), plane + (size_t)rc * WW + 4 * lkk, v);
        CP_COMMIT(); CP_WAIT0();
    }
    __syncthreads();

    for (int i = 0; i < NIT; ++i) {
        const int buf = i & 1;
        if (i + 1 < NIT) {
            int r = r0 + 4 * (i + 1) + lrw;
            bool v = r < HH;
            int rc = v ? r : HH - 1;
            cp16(s2u(&stage[buf ^ 1][lrw][4 * lkk]), plane + (size_t)rc * WW + 4 * lkk, v);
        }
        CP_COMMIT();
#pragma unroll
        for (int rw = 0; rw < 4; rw++) {
            float h = stage[buf][rw][t];
            u64 o = fir_push2(P, f2u(h, h * h), W6);
            *reinterpret_cast<u64*>(&vsb[rw][t]) = o;
        }
        __syncthreads();

        const int ro = r0 + 4 * i + hrw - 10;
        if (t < 184 && ro >= r0 && ro < r1) {
            u64 a[14];
#pragma unroll
            for (int ch = 0; ch < 7; ch++) {
                float4 u = *reinterpret_cast<const float4*>(&vsb[hrw][j0 + 2 * ch]);
                a[2 * ch]     = f2u(u.x, u.y);
                a[2 * ch + 1] = f2u(u.z, u.w);
            }
            float2 st[4];
#pragma unroll
            for (int cl = 0; cl < 4; cl++) {
                u64 s = f2u(0.f, 0.f);
#pragma unroll
                for (int k = 0; k < 11; k++) s = fma2(WP(k), a[cl + k], s);
                float mu, ss; u2f(s, mu, ss);
                st[cl] = make_float2(mu, ss - mu * mu);
            }
            float2* orow = &g_musig[((size_t)bf * HO + ro) * WO + j0];
            *reinterpret_cast<float4*>(orow) = make_float4(st[0].x, st[0].y, st[1].x, st[1].y);
            if (hcg < 45)
                *reinterpret_cast<float4*>(orow + 2) = make_float4(st[2].x, st[2].y, st[3].x, st[3].y);
        }
        CP_WAIT0();
        __syncthreads();
    }
}

// ---------------------------------------------------------------------------
// K2: main SSIM kernel. grid (c=64, b=8, 2 bands per launch), 192 threads.
// Static smem (41.6 KB). 2 barriers/iter. g_musig preloaded at iteration TOP
// (before the vertical phase) so its L2/DRAM latency is hidden under FIR work.
// Split into two launches (bandOff 0 / 2) so ncu's fixed capture window lands
// on a k2 instance.
// ---------------------------------------------------------------------------
__global__ void __launch_bounds__(192, 2) k2_ssim(const float* __restrict__ x,
                                                  const float* __restrict__ xf,
                                                  int bandOff) {
    const int c = blockIdx.x;
    const int b = blockIdx.y;
    const int band = blockIdx.z + bandOff;
    const int t = threadIdx.x;

    __shared__ float stage[2][4][4][WW];   // 24.0 KB
    __shared__ float vs[5][4][196];        // 15.3 KB
    __shared__ float red[3][192];          //  2.3 KB

    const int obs[5] = {0, 46, 92, 138, 182};
    const int o0 = obs[band], o1 = obs[band + 1];
    const int rin0 = o0;
    const int NIT = 14;

    const float* xp = x + ((size_t)(b * CC + c)) * HH * WW;
    const float* fp = xf + (size_t)b * FF * HH * WW;
    const float* plsrc[4] = { xp, fp, fp + (size_t)HH * WW, fp + (size_t)2 * HH * WW };

    const int lrw = t / 48, lkk = t % 48;
    const int hrw = t / 46, hcg = t % 46;
    const int j0 = 4 * hcg;

    float P[5][10];
#pragma unroll
    for (int q = 0; q < 5; q++)
#pragma unroll
        for (int m = 0; m < 10; m++) P[q][m] = 0.f;

    float acc0 = 0.f, acc1 = 0.f, acc2 = 0.f;

    {
        int r = rin0 + lrw;
        bool v = r < HH;
        int rc = v ? r : HH - 1;
#pragma unroll
        for (int l = 0; l < 4; l++)
            cp16(s2u(&stage[0][lrw][l][4 * lkk]),
                 plsrc[l] + (size_t)rc * WW + 4 * lkk, v);
        CP_COMMIT(); CP_WAIT0();
    }
    __syncthreads();

    for (int i = 0; i < NIT; ++i) {
        const int buf = i & 1;
        // prefetch next 4 rows into the other stage buffer
        if (i + 1 < NIT) {
            int r = rin0 + 4 * (i + 1) + lrw;
            bool v = r < HH;
            int rc = v ? r : HH - 1;
#pragma unroll
            for (int l = 0; l < 4; l++)
                cp16(s2u(&stage[buf ^ 1][lrw][l][4 * lkk]),
                     plsrc[l] + (size_t)rc * WW + 4 * lkk, v);
        }
        CP_COMMIT();

        // ---- EARLY g_musig preload for this iteration's horizontal ----
        const int ro = rin0 + 4 * i + hrw - 10;
        const bool hact = (t < 184 && ro >= o0 && ro < o1);
        float4 m01[3], m23[3];
        if (hact) {
#pragma unroll
            for (int f = 0; f < 3; f++) {
                const float4* mr = reinterpret_cast<const float4*>(
                    &g_musig[((size_t)(b * FF + f) * HO + ro) * WO + j0]);
                m01[f] = mr[0];
                m23[f] = mr[1];
            }
        }

        // ---- vertical FIRs, 4 rows x 5 quantities (hides the LDG latency) ----
#pragma unroll
        for (int rw = 0; rw < 4; rw++) {
            float xv = stage[buf][rw][0][t];
            float f0 = stage[buf][rw][1][t];
            float f1 = stage[buf][rw][2][t];
            float f2 = stage[buf][rw][3][t];
            vs[0][rw][t] = fir_push(P[0], xv);
            vs[1][rw][t] = fir_push(P[1], xv * xv);
            vs[2][rw][t] = fir_push(P[2], f0 * xv);
            vs[3][rw][t] = fir_push(P[3], f1 * xv);
            vs[4][rw][t] = fir_push(P[4], f2 * xv);
        }
        __syncthreads();

        // ---- horizontal + SSIM (1 row, 4 cols per thread) ----
        if (hact) {
            float Hq[5][4];
#pragma unroll
            for (int q = 0; q < 5; q++) {
                float v[16];
#pragma unroll
                for (int ch = 0; ch < 4; ch++) {
                    float4 u = *reinterpret_cast<const float4*>(&vs[q][hrw][j0 + 4 * ch]);
                    v[4*ch]=u.x; v[4*ch+1]=u.y; v[4*ch+2]=u.z; v[4*ch+3]=u.w;
                }
#pragma unroll
                for (int cl = 0; cl < 4; cl++) {
                    float s = 0.f;
#pragma unroll
                    for (int k = 0; k < 11; k++) s = fmaf(wt(k), v[cl + k], s);
                    Hq[q][cl] = s;
                }
            }
            // num/den per (f, col), edge cols masked to (0, 1)
            float num_[3][4], den_[3][4];
#pragma unroll
            for (int cl = 0; cl < 4; cl++) {
                float mux  = Hq[0][cl];
                float sigx = Hq[1][cl] - mux * mux;
                float mx2c = fmaf(mux, mux, C1S);
                float sxc  = sigx + C2S;
                const bool valid = (j0 + cl < WO);
#pragma unroll
                for (int f = 0; f < 3; f++) {
                    float muf, sigf;
                    if (cl == 0)      { muf = m01[f].x; sigf = m01[f].y; }
                    else if (cl == 1) { muf = m01[f].z; sigf = m01[f].w; }
                    else if (cl == 2) { muf = m23[f].x; sigf = m23[f].y; }
                    else              { muf = m23[f].z; sigf = m23[f].w; }
                    float tp   = muf * mux;
                    float sfx  = Hq[2 + f][cl] - tp;
                    float v1   = fmaf(2.f, sfx, C2S);
                    float v2   = sigf + sxc;
                    num_[f][cl] = valid ? fmaf(2.f, tp, C1S) * v1 : 0.f;
                    den_[f][cl] = valid ? fmaf(muf, muf, mx2c) * v2 : 1.f;
                }
            }
            // 4-way fraction merge: one RCP per f
#pragma unroll
            for (int f = 0; f < 3; f++) {
                float d0 = den_[f][0], d1 = den_[f][1];
                float d2 = den_[f][2], d3 = den_[f][3];
                float d01 = d0 * d1, d23 = d2 * d3;
                float s01 = fmaf(num_[f][0], d1, num_[f][1] * d0);
                float s23 = fmaf(num_[f][2], d3, num_[f][3] * d2);
                float N = fmaf(s01, d23, s23 * d01);
                float D = d01 * d23;
                float r = __fdividef(N, D);
                if (f == 0) acc0 += r; else if (f == 1) acc1 += r; else acc2 += r;
            }
        }
        CP_WAIT0();
        __syncthreads();
    }

    // ---- block reduce over 184 active threads ----
    red[0][t] = (t < 184) ? acc0 : 0.f;
    red[1][t] = (t < 184) ? acc1 : 0.f;
    red[2][t] = (t < 184) ? acc2 : 0.f;
    __syncthreads();
    if (t < 96) {
        const int f = t / 32, lane = t % 32;
        float s = red[f][lane] + red[f][lane + 32] + red[f][lane + 64] +
                  red[f][lane + 96] + red[f][lane + 128] + red[f][lane + 160];
#pragma unroll
        for (int off = 16; off > 0; off >>= 1)
            s += __shfl_down_sync(0xffffffffu, s, off);
        if (lane == 0)
            g_part[(((size_t)band * BB + b) * FF + f) * CC + c] = s;
    }
}

// ---------------------------------------------------------------------------
// K3: sum band partials -> ssim_info; conv + MLP + sigmoid. 1 block, 512 thr.
// ---------------------------------------------------------------------------
__global__ void __launch_bounds__(512) k3_gate(const float* __restrict__ sw,
                                               const float* __restrict__ W1,
                                               const float* __restrict__ b1,
                                               const float* __restrict__ W2,
                                               const float* __restrict__ b2,
                                               float* __restrict__ out,
                                               int out_size) {
    __shared__ float si[BB][FF][CC];
    __shared__ float gg[BB][CC];
    __shared__ float h1[BB][CC];

    const int t = threadIdx.x;
    const int b = t >> 6, c = t & 63;

    for (int i = t; i < BB * FF * CC; i += 512) {
        float s = g_part[i] + g_part[BB * FF * CC + i] +
                  g_part[2 * BB * FF * CC + i] + g_part[3 * BB * FF * CC + i];
        (&si[0][0][0])[i] = s * INV_NPIX;
    }
    __syncthreads();

    float s = 0.f;
#pragma unroll
    for (int f = 0; f < 3; f++) {
#pragma unroll
        for (int kk = 0; kk < 3; kk++) {
            int cc = c + kk - 1;
            if (cc >= 0 && cc < CC) s = fmaf(sw[f * 3 + kk], si[b][f][cc], s);
        }
    }
    gg[b][c] = fmaxf(s, 0.f);
    __syncthreads();

    float a = b1[c];
#pragma unroll 8
    for (int j = 0; j < CC; j++) a = fmaf(gg[b][j], W1[c * CC + j], a);
    h1[b][c] = fmaxf(a, 0.f);
    __syncthreads();

    float o = b2[c];
#pragma unroll 8
    for (int j = 0; j < CC; j++) o = fmaf(h1[b][j], W2[c * CC + j], o);
    out[b * CC + c] = 1.f / (1.f + expf(-o));

    if (out_size >= BB * CC + BB * FF * CC) {
        for (int i = t; i < BB * FF * CC; i += 512)
            out[BB * CC + i] = (&si[0][0][0])[i];
    }
}

// ---------------------------------------------------------------------------
extern "C" void kernel_launch(void* const* d_in, const int* in_sizes, int n_in,
                              void* d_out, int out_size) {
    const float* x  = (const float*)d_in[0];
    const float* xf = (const float*)d_in[1];
    const float* sw = (const float*)d_in[2];
    const float* W1 = (const float*)d_in[3];
    const float* b1 = (const float*)d_in[4];
    const float* W2 = (const float*)d_in[5];
    const float* b2 = (const float*)d_in[6];
    float* out = (float*)d_out;

    k1_musig<<<dim3(BB * FF, K1B), 192>>>(xf);
    k2_ssim<<<dim3(CC, BB, 2), 192>>>(x, xf, 0);   // bands 0,1
    k2_ssim<<<dim3(CC, BB, 2), 192>>>(x, xf, 2);   // bands 2,3
    k3_gate<<<1, 512>>>(sw, W1, b1, W2, b2, out, out_size);
}

// round 12
// speedup vs baseline: 1.3245x; 1.3245x over previous
#include <cuda_runtime.h>
#include <cstdint>

// Problem constants
#define BB 8
#define CC 64
#define FF 3
#define HH 192
#define WW 192
#define HO 182
#define WO 182
#define C1S 0.01f
#define C2S 0.09f
#define INV_NPIX (1.0f/33124.0f)
#define NBAND 4
#define K1B 12

typedef unsigned long long u64;

// mu_f/sig_f per (b,f) plane, packed {mu,sig}; +2 pad for float4 overread
__device__ __align__(16) float2 g_musig[BB * FF * HO * WO + 2];
// per-band partial ssim sums [band][B][F][C]
__device__ float g_part[NBAND * BB * FF * CC];

// 11-tap gaussian (sigma=1.5)
__device__ __forceinline__ float wt(int i) {
    switch (i) {
        case 0: case 10: return 0.00102838f;
        case 1: case 9:  return 0.00759876f;
        case 2: case 8:  return 0.03600077f;
        case 3: case 7:  return 0.10936069f;
        case 4: case 6:  return 0.21300553f;
        default:         return 0.26601173f;
    }
}

// ---- packed f32x2 helpers (k1 only) ----
__device__ __forceinline__ u64 f2u(float a, float b) {
    u64 r; asm("mov.b64 %0, {%1, %2};" : "=l"(r) : "f"(a), "f"(b)); return r;
}
__device__ __forceinline__ void u2f(u64 v, float& a, float& b) {
    asm("mov.b64 {%0, %1}, %2;" : "=f"(a), "=f"(b) : "l"(v));
}
__device__ __forceinline__ u64 fma2(u64 a, u64 b, u64 c) {
    u64 d; asm("fma.rn.f32x2 %0, %1, %2, %3;" : "=l"(d) : "l"(a), "l"(b), "l"(c)); return d;
}
__device__ __forceinline__ u64 mul2(u64 a, u64 b) {
    u64 d; asm("mul.rn.f32x2 %0, %1, %2;" : "=l"(d) : "l"(a), "l"(b)); return d;
}

// scalar transposed-FIR push (imm-form FFMA, zero weight registers, rt 1)
__device__ __forceinline__ float fir_push(float (&P)[10], float h) {
    float out = fmaf(wt(10), h, P[0]);
#pragma unroll
    for (int m = 0; m < 9; m++) P[m] = fmaf(wt(9 - m), h, P[m + 1]);
    P[9] = wt(0) * h;
    return out;
}

// packed transposed-FIR push; W6[k] = {wt(k),wt(k)} for k=0..5
#define WP(i) (W6[(i) < 6 ? (i) : 10 - (i)])
__device__ __forceinline__ u64 fir_push2(u64 (&P)[10], u64 h, const u64 (&W6)[6]) {
    u64 out = fma2(WP(10), h, P[0]);
#pragma unroll
    for (int m = 0; m < 9; m++) P[m] = fma2(WP(9 - m), h, P[m + 1]);
    P[9] = mul2(WP(0), h);
    return out;
}

__device__ __forceinline__ uint32_t s2u(const void* p) {
    return (uint32_t)__cvta_generic_to_shared(p);
}
__device__ __forceinline__ void cp16(uint32_t dst, const void* src, bool pred) {
    int sz = pred ? 16 : 0;
    asm volatile("cp.async.ca.shared.global [%0], [%1], 16, %2;\n"
                 :: "r"(dst), "l"(src), "r"(sz));
}
#define CP_COMMIT() asm volatile("cp.async.commit_group;\n" ::: "memory")
#define CP_WAIT0()  asm volatile("cp.async.wait_group 0;\n" ::: "memory")

// ---------------------------------------------------------------------------
// K1: mu_f/sig_f planes. grid (24, 12 bands), 192 threads. (unchanged)
// ---------------------------------------------------------------------------
__global__ void __launch_bounds__(192) k1_musig(const float* __restrict__ xf) {
    const int bf = blockIdx.x;
    const int band = blockIdx.y;
    const int t = threadIdx.x;

    __shared__ float stage[2][4][WW];
    __shared__ __align__(16) float2 vsb[4][196];   // packed {f_blur, ff_blur}

    const int r0 = 16 * band;
    const int r1 = (band == K1B - 1) ? HO : 16 * (band + 1);
    const int NIT = 7;

    const float* plane = xf + (size_t)bf * HH * WW;

    const int lrw = t / 48, lkk = t % 48;
    const int hrw = t / 46, hcg = t % 46;
    const int j0 = 4 * hcg;

    u64 W6[6];
#pragma unroll
    for (int k = 0; k < 6; k++) W6[k] = f2u(wt(k), wt(k));

    u64 P[10];
#pragma unroll
    for (int m = 0; m < 10; m++) P[m] = f2u(0.f, 0.f);

    {
        int r = r0 + lrw;
        bool v = r < HH;
        int rc = v ? r : HH - 1;
        cp16(s2u(&stage[0][lrw][4 * lkk]), plane + (size_t)rc * WW + 4 * lkk, v);
        CP_COMMIT(); CP_WAIT0();
    }
    __syncthreads();

    for (int i = 0; i < NIT; ++i) {
        const int buf = i & 1;
        if (i + 1 < NIT) {
            int r = r0 + 4 * (i + 1) + lrw;
            bool v = r < HH;
            int rc = v ? r : HH - 1;
            cp16(s2u(&stage[buf ^ 1][lrw][4 * lkk]), plane + (size_t)rc * WW + 4 * lkk, v);
        }
        CP_COMMIT();
#pragma unroll
        for (int rw = 0; rw < 4; rw++) {
            float h = stage[buf][rw][t];
            u64 o = fir_push2(P, f2u(h, h * h), W6);
            *reinterpret_cast<u64*>(&vsb[rw][t]) = o;
        }
        __syncthreads();

        const int ro = r0 + 4 * i + hrw - 10;
        if (t < 184 && ro >= r0 && ro < r1) {
            u64 a[14];
#pragma unroll
            for (int ch = 0; ch < 7; ch++) {
                float4 u = *reinterpret_cast<const float4*>(&vsb[hrw][j0 + 2 * ch]);
                a[2 * ch]     = f2u(u.x, u.y);
                a[2 * ch + 1] = f2u(u.z, u.w);
            }
            float2 st[4];
#pragma unroll
            for (int cl = 0; cl < 4; cl++) {
                u64 s = f2u(0.f, 0.f);
#pragma unroll
                for (int k = 0; k < 11; k++) s = fma2(WP(k), a[cl + k], s);
                float mu, ss; u2f(s, mu, ss);
                st[cl] = make_float2(mu, ss - mu * mu);
            }
            float2* orow = &g_musig[((size_t)bf * HO + ro) * WO + j0];
            *reinterpret_cast<float4*>(orow) = make_float4(st[0].x, st[0].y, st[1].x, st[1].y);
            if (hcg < 45)
                *reinterpret_cast<float4*>(orow + 2) = make_float4(st[2].x, st[2].y, st[3].x, st[3].y);
        }
        CP_WAIT0();
        __syncthreads();
    }
}

// ---------------------------------------------------------------------------
// K2: main SSIM kernel. grid (c=64, b=8, band=4), 192 threads.
// Static smem (41.6 KB). g_musig preloaded at iteration TOP so its latency
// hides under the vertical FIR phase.
// ---------------------------------------------------------------------------
__global__ void __launch_bounds__(192, 2) k2_ssim(const float* __restrict__ x,
                                                  const float* __restrict__ xf) {
    const int c = blockIdx.x;
    const int b = blockIdx.y;
    const int band = blockIdx.z;
    const int t = threadIdx.x;

    __shared__ float stage[2][4][4][WW];   // 24.0 KB
    __shared__ float vs[5][4][196];        // 15.3 KB
    __shared__ float red[3][192];          //  2.3 KB

    const int obs[5] = {0, 46, 92, 138, 182};
    const int o0 = obs[band], o1 = obs[band + 1];
    const int rin0 = o0;
    const int NIT = 14;

    const float* xp = x + ((size_t)(b * CC + c)) * HH * WW;
    const float* fp = xf + (size_t)b * FF * HH * WW;
    const float* plsrc[4] = { xp, fp, fp + (size_t)HH * WW, fp + (size_t)2 * HH * WW };

    const int lrw = t / 48, lkk = t % 48;
    const int hrw = t / 46, hcg = t % 46;
    const int j0 = 4 * hcg;

    float P[5][10];
#pragma unroll
    for (int q = 0; q < 5; q++)
#pragma unroll
        for (int m = 0; m < 10; m++) P[q][m] = 0.f;

    float acc0 = 0.f, acc1 = 0.f, acc2 = 0.f;

    {
        int r = rin0 + lrw;
        bool v = r < HH;
        int rc = v ? r : HH - 1;
#pragma unroll
        for (int l = 0; l < 4; l++)
            cp16(s2u(&stage[0][lrw][l][4 * lkk]),
                 plsrc[l] + (size_t)rc * WW + 4 * lkk, v);
        CP_COMMIT(); CP_WAIT0();
    }
    __syncthreads();

    for (int i = 0; i < NIT; ++i) {
        const int buf = i & 1;
        if (i + 1 < NIT) {
            int r = rin0 + 4 * (i + 1) + lrw;
            bool v = r < HH;
            int rc = v ? r : HH - 1;
#pragma unroll
            for (int l = 0; l < 4; l++)
                cp16(s2u(&stage[buf ^ 1][lrw][l][4 * lkk]),
                     plsrc[l] + (size_t)rc * WW + 4 * lkk, v);
        }
        CP_COMMIT();

        // ---- EARLY g_musig preload for this iteration's horizontal ----
        const int ro = rin0 + 4 * i + hrw - 10;
        const bool hact = (t < 184 && ro >= o0 && ro < o1);
        float4 m01[3], m23[3];
        if (hact) {
#pragma unroll
            for (int f = 0; f < 3; f++) {
                const float4* mr = reinterpret_cast<const float4*>(
                    &g_musig[((size_t)(b * FF + f) * HO + ro) * WO + j0]);
                m01[f] = mr[0];
                m23[f] = mr[1];
            }
        }

        // ---- vertical FIRs, 4 rows x 5 quantities ----
#pragma unroll
        for (int rw = 0; rw < 4; rw++) {
            float xv = stage[buf][rw][0][t];
            float f0 = stage[buf][rw][1][t];
            float f1 = stage[buf][rw][2][t];
            float f2 = stage[buf][rw][3][t];
            vs[0][rw][t] = fir_push(P[0], xv);
            vs[1][rw][t] = fir_push(P[1], xv * xv);
            vs[2][rw][t] = fir_push(P[2], f0 * xv);
            vs[3][rw][t] = fir_push(P[3], f1 * xv);
            vs[4][rw][t] = fir_push(P[4], f2 * xv);
        }
        __syncthreads();

        // ---- horizontal + SSIM (1 row, 4 cols per thread) ----
        if (hact) {
            float Hq[5][4];
#pragma unroll
            for (int q = 0; q < 5; q++) {
                float v[16];
#pragma unroll
                for (int ch = 0; ch < 4; ch++) {
                    float4 u = *reinterpret_cast<const float4*>(&vs[q][hrw][j0 + 4 * ch]);
                    v[4*ch]=u.x; v[4*ch+1]=u.y; v[4*ch+2]=u.z; v[4*ch+3]=u.w;
                }
#pragma unroll
                for (int cl = 0; cl < 4; cl++) {
                    float s = 0.f;
#pragma unroll
                    for (int k = 0; k < 11; k++) s = fmaf(wt(k), v[cl + k], s);
                    Hq[q][cl] = s;
                }
            }
            float num_[3][4], den_[3][4];
#pragma unroll
            for (int cl = 0; cl < 4; cl++) {
                float mux  = Hq[0][cl];
                float sigx = Hq[1][cl] - mux * mux;
                float mx2c = fmaf(mux, mux, C1S);
                float sxc  = sigx + C2S;
                const bool valid = (j0 + cl < WO);
#pragma unroll
                for (int f = 0; f < 3; f++) {
                    float muf, sigf;
                    if (cl == 0)      { muf = m01[f].x; sigf = m01[f].y; }
                    else if (cl == 1) { muf = m01[f].z; sigf = m01[f].w; }
                    else if (cl == 2) { muf = m23[f].x; sigf = m23[f].y; }
                    else              { muf = m23[f].z; sigf = m23[f].w; }
                    float tp   = muf * mux;
                    float sfx  = Hq[2 + f][cl] - tp;
                    float v1   = fmaf(2.f, sfx, C2S);
                    float v2   = sigf + sxc;
                    num_[f][cl] = valid ? fmaf(2.f, tp, C1S) * v1 : 0.f;
                    den_[f][cl] = valid ? fmaf(muf, muf, mx2c) * v2 : 1.f;
                }
            }
#pragma unroll
            for (int f = 0; f < 3; f++) {
                float d0 = den_[f][0], d1 = den_[f][1];
                float d2 = den_[f][2], d3 = den_[f][3];
                float d01 = d0 * d1, d23 = d2 * d3;
                float s01 = fmaf(num_[f][0], d1, num_[f][1] * d0);
                float s23 = fmaf(num_[f][2], d3, num_[f][3] * d2);
                float N = fmaf(s01, d23, s23 * d01);
                float D = d01 * d23;
                float r = __fdividef(N, D);
                if (f == 0) acc0 += r; else if (f == 1) acc1 += r; else acc2 += r;
            }
        }
        CP_WAIT0();
        __syncthreads();
    }

    // ---- block reduce over 184 active threads ----
    red[0][t] = (t < 184) ? acc0 : 0.f;
    red[1][t] = (t < 184) ? acc1 : 0.f;
    red[2][t] = (t < 184) ? acc2 : 0.f;
    __syncthreads();
    if (t < 96) {
        const int f = t / 32, lane = t % 32;
        float s = red[f][lane] + red[f][lane + 32] + red[f][lane + 64] +
                  red[f][lane + 96] + red[f][lane + 128] + red[f][lane + 160];
#pragma unroll
        for (int off = 16; off > 0; off >>= 1)
            s += __shfl_down_sync(0xffffffffu, s, off);
        if (lane == 0)
            g_part[(((size_t)band * BB + b) * FF + f) * CC + c] = s;
    }
}

// ---------------------------------------------------------------------------
// K3: epilogue. grid (8) — ONE BLOCK PER BATCH, 256 threads.
// W1/W2 staged into smem transposed (pitch 65, conflict-free), coalesced LDG.
// ---------------------------------------------------------------------------
__global__ void __launch_bounds__(256) k3_gate(const float* __restrict__ sw,
                                               const float* __restrict__ W1,
                                               const float* __restrict__ b1,
                                               const float* __restrict__ W2,
                                               const float* __restrict__ b2,
                                               float* __restrict__ out,
                                               int out_size) {
    __shared__ float W1s[CC * 65];   // transposed, pitch 65: W1s[j*65+c] = W1[c*64+j]
    __shared__ float W2s[CC * 65];
    __shared__ float si[FF][CC];
    __shared__ float gg[CC];
    __shared__ float h1[CC];

    const int b = blockIdx.x;
    const int t = threadIdx.x;

    // stage W1/W2 coalesced (float4), scatter transposed into smem
    for (int i4 = t; i4 < CC * CC / 4; i4 += 256) {
        int i = 4 * i4;
        int cw = i >> 6, jw = i & 63;       // W[cw][jw..jw+3]
        float4 w1 = *reinterpret_cast<const float4*>(W1 + i);
        float4 w2 = *reinterpret_cast<const float4*>(W2 + i);
        W1s[(jw + 0) * 65 + cw] = w1.x; W1s[(jw + 1) * 65 + cw] = w1.y;
        W1s[(jw + 2) * 65 + cw] = w1.z; W1s[(jw + 3) * 65 + cw] = w1.w;
        W2s[(jw + 0) * 65 + cw] = w2.x; W2s[(jw + 1) * 65 + cw] = w2.y;
        W2s[(jw + 2) * 65 + cw] = w2.z; W2s[(jw + 3) * 65 + cw] = w2.w;
    }
    // band-sum ssim partials for this b and write ssim output
    for (int i = t; i < FF * CC; i += 256) {
        const int base = b * FF * CC + i;
        float s = g_part[base] + g_part[BB * FF * CC + base] +
                  g_part[2 * BB * FF * CC + base] + g_part[3 * BB * FF * CC + base];
        s *= INV_NPIX;
        (&si[0][0])[i] = s;
        if (out_size >= BB * CC + BB * FF * CC)
            out[BB * CC + base] = s;
    }
    __syncthreads();

    if (t < CC) {
        const int c = t;
        // conv (3,1) over C, in-channels F, + relu
        float s = 0.f;
#pragma unroll
        for (int f = 0; f < 3; f++) {
#pragma unroll
            for (int kk = 0; kk < 3; kk++) {
                int cc = c + kk - 1;
                if (cc >= 0 && cc < CC) s = fmaf(sw[f * 3 + kk], si[f][cc], s);
            }
        }
        gg[c] = fmaxf(s, 0.f);
    }
    __syncthreads();

    if (t < CC) {
        const int c = t;
        float a = b1[c];
#pragma unroll 16
        for (int j = 0; j < CC; j++) a = fmaf(gg[j], W1s[j * 65 + c], a);
        h1[c] = fmaxf(a, 0.f);
    }
    __syncthreads();

    if (t < CC) {
        const int c = t;
        float o = b2[c];
#pragma unroll 16
        for (int j = 0; j < CC; j++) o = fmaf(h1[j], W2s[j * 65 + c], o);
        out[b * CC + c] = 1.f / (1.f + expf(-o));
    }
}

// ---------------------------------------------------------------------------
extern "C" void kernel_launch(void* const* d_in, const int* in_sizes, int n_in,
                              void* d_out, int out_size) {
    const float* x  = (const float*)d_in[0];
    const float* xf = (const float*)d_in[1];
    const float* sw = (const float*)d_in[2];
    const float* W1 = (const float*)d_in[3];
    const float* b1 = (const float*)d_in[4];
    const float* W2 = (const float*)d_in[5];
    const float* b2 = (const float*)d_in[6];
    float* out = (float*)d_out;

    k1_musig<<<dim3(BB * FF, K1B), 192>>>(xf);
    k2_ssim<<<dim3(CC, BB, NBAND), 192>>>(x, xf);
    k3_gate<<<BB, 256>>>(sw, W1, b1, W2, b2, out, out_size);
}